// round 2
// baseline (speedup 1.0000x reference)
#include <cuda_runtime.h>

// Problem constants
#define BB   64
#define CC   256
#define NTOK 1600      // T*V
#define VQ   25
#define HH   8
#define HD   32
#define RR   200       // HH*VQ real score rows
#define RP   256       // padded rows

// Scratch (device globals — allocation-free rule). Zero-initialized at load;
// pad rows of g_Qe are re-zeroed every launch for determinism.
__device__ float g_Qe[BB * RP * CC];    // per-b effective Q (rows 200..255 zero)
__device__ float g_S [BB * RP * NTOK];  // scores -> probabilities (in place)
__device__ float g_Y [BB * RP * CC];    // Y = P @ X^T
__device__ float g_We[HH * CC * CC];    // folded Wv->proj weights per head

// ---------------- packed fp32 helpers (FFMA2 path) ----------------
__device__ __forceinline__ unsigned long long pk2(float x, float y) {
    unsigned long long r;
    asm("mov.b64 %0, {%1, %2};" : "=l"(r) : "f"(x), "f"(y));
    return r;
}
__device__ __forceinline__ void unpk(unsigned long long v, float& x, float& y) {
    asm("mov.b64 {%0, %1}, %2;" : "=f"(x), "=f"(y) : "l"(v));
}
__device__ __forceinline__ void ffma2(unsigned long long& d, unsigned long long a, unsigned long long b) {
    asm("fma.rn.f32x2 %0, %1, %2, %0;" : "+l"(d) : "l"(a), "l"(b));
}

// ---------------------------------------------------------------
// Weff[h][co][c] = sum_d proj_w[co][h*32+d] * v_w[h*32+d][c]
// ---------------------------------------------------------------
__global__ __launch_bounds__(256)
void weff_kernel(const float* __restrict__ pw, const float* __restrict__ vw) {
    const int h   = blockIdx.x;
    const int co0 = blockIdx.y * 32;
    const int c   = threadIdx.x;
    float vv[HD];
#pragma unroll
    for (int d = 0; d < HD; d++) vv[d] = vw[(h * HD + d) * CC + c];
    for (int i = 0; i < 32; i++) {
        const int co = co0 + i;
        float a = 0.f;
#pragma unroll
        for (int d = 0; d < HD; d++) a += pw[co * CC + h * HD + d] * vv[d];
        g_We[(h * CC + co) * CC + c] = a;
    }
}

// ---------------------------------------------------------------
// Qeff: per b. Stage1: Q[v][col] = sum_c2 x_cls[b][c2][v]*q_w[col][c2],
// scaled by temp[h]/sqrt(hd). Stage2: Qeff[h*25+v][c] = sum_d Q[v][h*32+d]*k_w[h*32+d][c].
// ---------------------------------------------------------------
__global__ __launch_bounds__(256)
void qeff_kernel(const float* __restrict__ x_cls,
                 const float* __restrict__ qw,
                 const float* __restrict__ kw,
                 const float* __restrict__ temp) {
    const int b = blockIdx.x;
    const int t = threadIdx.x;
    __shared__ float buf[6528];   // reused: xs[c2*25+v] then Qs[v*260+col]

    for (int i = t; i < CC * VQ; i += 256) buf[i] = x_cls[b * CC * VQ + i];
    __syncthreads();

    float acc[VQ];
#pragma unroll
    for (int v = 0; v < VQ; v++) acc[v] = 0.f;
    const float* wrow = qw + t * CC;
    for (int c2 = 0; c2 < CC; c2++) {
        float w = wrow[c2];
#pragma unroll
        for (int v = 0; v < VQ; v++) acc[v] += w * buf[c2 * VQ + v];
    }
    const float s = temp[t >> 5] * 0.17677669529663687f;  // 1/sqrt(32)
    __syncthreads();
#pragma unroll
    for (int v = 0; v < VQ; v++) buf[v * 260 + t] = acc[v] * s;
    __syncthreads();

    float* Qe = g_Qe + b * RP * CC;
    for (int h = 0; h < HH; h++) {
        float kv[HD];
#pragma unroll
        for (int d = 0; d < HD; d++) kv[d] = kw[(h * HD + d) * CC + t];
        for (int v = 0; v < VQ; v++) {
            float a = 0.f;
#pragma unroll
            for (int d = 0; d < HD; d++) a += buf[v * 260 + h * HD + d] * kv[d];
            Qe[(h * VQ + v) * CC + t] = a;
        }
    }
    for (int r = RR; r < RP; r++) Qe[r * CC + t] = 0.f;   // pad rows -> zero scores
}

// ---------------------------------------------------------------
// GEMM1: S[b][r][n] = sum_c Qe[b][r][c] * X[b][c][n]
// Block tile 128(r) x 64(n), K-step 16, 128 threads, FFMA2 microtile.
// ---------------------------------------------------------------
__global__ __launch_bounds__(128, 4)
void gemm1_kernel(const float* __restrict__ X) {
    const int b  = blockIdx.z;
    const int r0 = blockIdx.y * 128;
    const int n0 = blockIdx.x * 64;

    __shared__ __align__(16) float Xs[16][64];
    __shared__ __align__(16) float Wt[16][128];

    const int tid = threadIdx.x;
    const int tx = tid & 7;
    const int ty = tid >> 3;

    const float* Xb = X + b * (CC * NTOK) + n0;
    const float* Wb = g_Qe + b * RP * CC;

    unsigned long long acc[32];
#pragma unroll
    for (int i = 0; i < 32; i++) acc[i] = 0ull;

    const int lr = tid >> 3;
    const int lc = (tid & 7) * 4;

    for (int k0 = 0; k0 < CC; k0 += 16) {
        float4 xa  = *(const float4*)(Xb + (k0 + lr) * NTOK + lc);
        float4 xb4 = *(const float4*)(Xb + (k0 + lr) * NTOK + lc + 32);
        *(float4*)&Xs[lr][lc]      = xa;
        *(float4*)&Xs[lr][lc + 32] = xb4;
        const float* wrow = Wb + (r0 + tid) * CC + k0;
#pragma unroll
        for (int g = 0; g < 4; g++) {
            float4 w4 = *(const float4*)(wrow + g * 4);
            Wt[g * 4 + 0][tid] = w4.x;
            Wt[g * 4 + 1][tid] = w4.y;
            Wt[g * 4 + 2][tid] = w4.z;
            Wt[g * 4 + 3][tid] = w4.w;
        }
        __syncthreads();

#pragma unroll
        for (int kk = 0; kk < 16; kk++) {
            float4 x0 = *(const float4*)&Xs[kk][tx * 4];
            float4 x1 = *(const float4*)&Xs[kk][tx * 4 + 32];
            unsigned long long px[8];
            px[0] = pk2(x0.x, x0.x); px[1] = pk2(x0.y, x0.y);
            px[2] = pk2(x0.z, x0.z); px[3] = pk2(x0.w, x0.w);
            px[4] = pk2(x1.x, x1.x); px[5] = pk2(x1.y, x1.y);
            px[6] = pk2(x1.z, x1.z); px[7] = pk2(x1.w, x1.w);
            const ulonglong2* wp = (const ulonglong2*)&Wt[kk][ty * 8];
            ulonglong2 a01 = wp[0];
            ulonglong2 a23 = wp[1];
            unsigned long long av[4] = {a01.x, a01.y, a23.x, a23.y};
#pragma unroll
            for (int cp = 0; cp < 4; cp++) {
#pragma unroll
                for (int j = 0; j < 8; j++)
                    ffma2(acc[cp * 8 + j], av[cp], px[j]);
            }
        }
        __syncthreads();
    }

    float* Ob = g_S + b * RP * NTOK + n0;
#pragma unroll
    for (int cp = 0; cp < 4; cp++) {
        float r0v[8], r1v[8];
#pragma unroll
        for (int j = 0; j < 8; j++) unpk(acc[cp * 8 + j], r0v[j], r1v[j]);
        const int row = r0 + ty * 8 + cp * 2;
        *(float4*)(Ob + row * NTOK + tx * 4)            = make_float4(r0v[0], r0v[1], r0v[2], r0v[3]);
        *(float4*)(Ob + row * NTOK + tx * 4 + 32)       = make_float4(r0v[4], r0v[5], r0v[6], r0v[7]);
        *(float4*)(Ob + (row + 1) * NTOK + tx * 4)      = make_float4(r1v[0], r1v[1], r1v[2], r1v[3]);
        *(float4*)(Ob + (row + 1) * NTOK + tx * 4 + 32) = make_float4(r1v[4], r1v[5], r1v[6], r1v[7]);
    }
}

// ---------------------------------------------------------------
// Row softmax over g_S rows r<200, in place. One warp per row.
// ---------------------------------------------------------------
__global__ __launch_bounds__(256)
void softmax_kernel() {
    const int wid  = threadIdx.x >> 5;
    const int lane = threadIdx.x & 31;
    const int r = blockIdx.x * 8 + wid;        // < 200
    const int b = blockIdx.y;
    float* p = g_S + (b * RP + r) * NTOK;

    float v[50];
    float mx = -1e30f;
#pragma unroll
    for (int i = 0; i < 50; i++) { v[i] = p[i * 32 + lane]; mx = fmaxf(mx, v[i]); }
#pragma unroll
    for (int o = 16; o; o >>= 1) mx = fmaxf(mx, __shfl_xor_sync(0xffffffffu, mx, o));
    float s = 0.f;
#pragma unroll
    for (int i = 0; i < 50; i++) { float e = __expf(v[i] - mx); v[i] = e; s += e; }
#pragma unroll
    for (int o = 16; o; o >>= 1) s += __shfl_xor_sync(0xffffffffu, s, o);
    const float inv = 1.f / s;
#pragma unroll
    for (int i = 0; i < 50; i++) p[i * 32 + lane] = v[i] * inv;
}

// ---------------------------------------------------------------
// GEMM2: Y[b][r][c] = sum_n P[b][r][n] * X[b][c][n]   (contract n=1600)
// Block tile 128(r) x 64(c), K-step 16.
// ---------------------------------------------------------------
__global__ __launch_bounds__(128, 4)
void gemm2_kernel(const float* __restrict__ X) {
    const int b  = blockIdx.z;
    const int r0 = blockIdx.y * 128;
    const int c0 = blockIdx.x * 64;

    __shared__ __align__(16) float Pt[16][128];
    __shared__ __align__(16) float Xs[16][64];

    const int tid = threadIdx.x;
    const int tx = tid & 7;
    const int ty = tid >> 3;

    const float* Pb = g_S + (b * RP + r0) * NTOK;
    const float* Xb = X + b * (CC * NTOK) + c0 * NTOK;

    unsigned long long acc[32];
#pragma unroll
    for (int i = 0; i < 32; i++) acc[i] = 0ull;

    const int lc = tid & 63;
    const int lh = tid >> 6;

    for (int k0 = 0; k0 < NTOK; k0 += 16) {
        const float* prow = Pb + tid * NTOK + k0;
#pragma unroll
        for (int g = 0; g < 4; g++) {
            float4 w4 = *(const float4*)(prow + g * 4);
            Pt[g * 4 + 0][tid] = w4.x;
            Pt[g * 4 + 1][tid] = w4.y;
            Pt[g * 4 + 2][tid] = w4.z;
            Pt[g * 4 + 3][tid] = w4.w;
        }
        const float* xrow = Xb + lc * NTOK + k0 + lh * 8;
        float4 a4 = *(const float4*)(xrow);
        float4 b4 = *(const float4*)(xrow + 4);
        Xs[lh * 8 + 0][lc] = a4.x; Xs[lh * 8 + 1][lc] = a4.y;
        Xs[lh * 8 + 2][lc] = a4.z; Xs[lh * 8 + 3][lc] = a4.w;
        Xs[lh * 8 + 4][lc] = b4.x; Xs[lh * 8 + 5][lc] = b4.y;
        Xs[lh * 8 + 6][lc] = b4.z; Xs[lh * 8 + 7][lc] = b4.w;
        __syncthreads();

#pragma unroll
        for (int kk = 0; kk < 16; kk++) {
            float4 x0 = *(const float4*)&Xs[kk][tx * 4];
            float4 x1 = *(const float4*)&Xs[kk][tx * 4 + 32];
            unsigned long long px[8];
            px[0] = pk2(x0.x, x0.x); px[1] = pk2(x0.y, x0.y);
            px[2] = pk2(x0.z, x0.z); px[3] = pk2(x0.w, x0.w);
            px[4] = pk2(x1.x, x1.x); px[5] = pk2(x1.y, x1.y);
            px[6] = pk2(x1.z, x1.z); px[7] = pk2(x1.w, x1.w);
            const ulonglong2* wp = (const ulonglong2*)&Pt[kk][ty * 8];
            ulonglong2 a01 = wp[0];
            ulonglong2 a23 = wp[1];
            unsigned long long av[4] = {a01.x, a01.y, a23.x, a23.y};
#pragma unroll
            for (int cp = 0; cp < 4; cp++) {
#pragma unroll
                for (int j = 0; j < 8; j++)
                    ffma2(acc[cp * 8 + j], av[cp], px[j]);
            }
        }
        __syncthreads();
    }

    float* Ob = g_Y + b * RP * CC;
#pragma unroll
    for (int cp = 0; cp < 4; cp++) {
        float r0v[8], r1v[8];
#pragma unroll
        for (int j = 0; j < 8; j++) unpk(acc[cp * 8 + j], r0v[j], r1v[j]);
        const int row = r0 + ty * 8 + cp * 2;
        *(float4*)(Ob + row * CC + c0 + tx * 4)            = make_float4(r0v[0], r0v[1], r0v[2], r0v[3]);
        *(float4*)(Ob + row * CC + c0 + tx * 4 + 32)       = make_float4(r0v[4], r0v[5], r0v[6], r0v[7]);
        *(float4*)(Ob + (row + 1) * CC + c0 + tx * 4)      = make_float4(r1v[0], r1v[1], r1v[2], r1v[3]);
        *(float4*)(Ob + (row + 1) * CC + c0 + tx * 4 + 32) = make_float4(r1v[4], r1v[5], r1v[6], r1v[7]);
    }
}

// ---------------------------------------------------------------
// Final: out[b][co][v] = proj_b[co] + sum_h sum_c We[h][co][c]*Y[b][h*25+v][c]
// grid (64, 4): blockIdx.y selects v-phase (v = gy + 4k).
// ---------------------------------------------------------------
__global__ __launch_bounds__(256)
void final_kernel(const float* __restrict__ pb, float* __restrict__ out) {
    const int b  = blockIdx.x;
    const int gy = blockIdx.y;
    const int t  = threadIdx.x;
    __shared__ float ys[256 * 27 + 32];

    const int nv = (gy == 0) ? 7 : 6;
    float acc[7];
    const float bias = pb[t];
#pragma unroll
    for (int k = 0; k < 7; k++) acc[k] = bias;

    for (int h = 0; h < HH; h++) {
        __syncthreads();
        for (int i = t; i < VQ * CC; i += 256) {
            int v = i >> 8, c = i & 255;
            ys[c * 27 + v] = g_Y[(b * RP + h * VQ + v) * CC + c];
        }
        __syncthreads();
        const float* we = g_We + (h * CC + t) * CC;
        for (int c = 0; c < CC; c++) {
            float w = we[c];
#pragma unroll
            for (int k = 0; k < 7; k++)
                acc[k] += w * ys[c * 27 + gy + 4 * k];
        }
    }
    for (int k = 0; k < nv; k++)
        out[b * (CC * VQ) + t * VQ + gy + 4 * k] = acc[k];
}

// ---------------------------------------------------------------
extern "C" void kernel_launch(void* const* d_in, const int* in_sizes, int n_in,
                              void* d_out, int out_size) {
    (void)in_sizes; (void)n_in; (void)out_size;
    const float* x_cls   = (const float*)d_in[0];
    const float* x_patch = (const float*)d_in[1];
    const float* q_w     = (const float*)d_in[2];
    const float* k_w     = (const float*)d_in[3];
    const float* v_w     = (const float*)d_in[4];
    const float* temp    = (const float*)d_in[5];
    const float* proj_w  = (const float*)d_in[6];
    const float* proj_b  = (const float*)d_in[7];
    float* out = (float*)d_out;

    weff_kernel<<<dim3(HH, 8), 256>>>(proj_w, v_w);
    qeff_kernel<<<BB, 256>>>(x_cls, q_w, k_w, temp);
    gemm1_kernel<<<dim3(NTOK / 64, RP / 128, BB), 128>>>(x_patch);
    softmax_kernel<<<dim3(RR / 8, BB), 256>>>();
    gemm2_kernel<<<dim3(CC / 64, RP / 128, BB), 128>>>(x_patch);
    final_kernel<<<dim3(BB, 4), 256>>>(proj_b, out);
}

// round 6
// speedup vs baseline: 1.1065x; 1.1065x over previous
#include <cuda_runtime.h>
#include <cuda_bf16.h>
#include <cstdint>

#define BB   64
#define CC   256
#define NTOK 1600
#define VQ   25
#define HH   8
#define HD   32
#define RR   200
#define RP   256

typedef __nv_bfloat16 bf;

// -------- device scratch (allocation-free rule; zero-init at load) --------
__device__ __align__(16) bf    g_Qeh[BB * RP * CC];   // pad rows 200..255 stay 0
__device__ __align__(16) bf    g_Qel[BB * RP * CC];
__device__ __align__(16) bf    g_Xh [BB * CC * NTOK];
__device__ __align__(16) bf    g_Xl [BB * CC * NTOK];
__device__ __align__(16) bf    g_Ph [BB * RP * NTOK]; // pad rows stay 0
__device__ __align__(16) bf    g_Pl [BB * RP * NTOK];
__device__ __align__(16) float g_S  [BB * RP * NTOK];
__device__ __align__(16) float g_Y  [BB * RP * CC];
__device__ __align__(16) float g_We [HH * CC * CC];

// ==================== PTX helpers (baseline ISA only) ====================
__device__ __forceinline__ uint32_t smem_u32(const void* p) {
    uint32_t a;
    asm("{ .reg .u64 t; cvta.to.shared.u64 t, %1; cvt.u32.u64 %0, t; }" : "=r"(a) : "l"(p));
    return a;
}
__device__ __forceinline__ void ldsm4(uint32_t* r, uint32_t a) {
    asm volatile("ldmatrix.sync.aligned.m8n8.x4.shared.b16 {%0,%1,%2,%3}, [%4];"
                 : "=r"(r[0]), "=r"(r[1]), "=r"(r[2]), "=r"(r[3]) : "r"(a));
}
__device__ __forceinline__ void ldsm2(uint32_t* r, uint32_t a) {
    asm volatile("ldmatrix.sync.aligned.m8n8.x2.shared.b16 {%0,%1}, [%2];"
                 : "=r"(r[0]), "=r"(r[1]) : "r"(a));
}
__device__ __forceinline__ void ldsm2t(uint32_t* r, uint32_t a) {
    asm volatile("ldmatrix.sync.aligned.m8n8.x2.trans.shared.b16 {%0,%1}, [%2];"
                 : "=r"(r[0]), "=r"(r[1]) : "r"(a));
}
__device__ __forceinline__ void mma_bf16(float* c, const uint32_t* a, const uint32_t* b) {
    asm volatile("mma.sync.aligned.m16n8k16.row.col.f32.bf16.bf16.f32 "
                 "{%0,%1,%2,%3}, {%4,%5,%6,%7}, {%8,%9}, {%0,%1,%2,%3};"
                 : "+f"(c[0]), "+f"(c[1]), "+f"(c[2]), "+f"(c[3])
                 : "r"(a[0]), "r"(a[1]), "r"(a[2]), "r"(a[3]), "r"(b[0]), "r"(b[1]));
}
__device__ __forceinline__ void split_bf(float v, bf& h, bf& l) {
    h = __float2bfloat16(v);
    l = __float2bfloat16(v - __bfloat162float(h));
}

// copy a [rows x 64] bf16 tile (row stride in elems) into SW128-swizzled smem
__device__ __forceinline__ void copy_tile(char* dst, const bf* __restrict__ src,
                                          int rows, long long stride, int tid) {
    for (int idx = tid; idx < rows * 8; idx += 256) {
        int r = idx >> 3, c = idx & 7;
        uint4 v = *(const uint4*)(src + (long long)r * stride + c * 8);
        uint32_t off = (uint32_t)(r * 128 + c * 16);
        off ^= (off >> 3) & 0x70;
        *(uint4*)(dst + off) = v;
    }
}

// ==================== GEMM1: S[b][r][n] = Qe @ X (contract c=256) ====================
// Block 128(r) x 160(n); warps 2(m) x 4(n) -> warp tile 64 x 40.
// A: K-major swizzled [128][64]; B from X[c][n] via padded rows + ldmatrix.trans.
#define B1P 336   // padded B row bytes: 168 bf16
__global__ __launch_bounds__(256, 1)
void gemm1_mma() {
    extern __shared__ char smem[];
    constexpr int A_HI = 0, A_LO = 16384, B_HI = 32768, B_LO = 32768 + 64 * B1P;
    const int b = blockIdx.z, r0 = blockIdx.y * 128, n0 = blockIdx.x * 160;
    const int tid = threadIdx.x, lane = tid & 31, wid = tid >> 5;
    const int wm = wid >> 2, wn = wid & 3;
    const uint32_t sb = smem_u32(smem);

    float acc[4][5][4];
#pragma unroll
    for (int i = 0; i < 4; i++)
#pragma unroll
        for (int j = 0; j < 5; j++)
#pragma unroll
            for (int k = 0; k < 4; k++) acc[i][j][k] = 0.f;

    const bf* Ah = g_Qeh + ((long long)b * RP + r0) * CC;
    const bf* Al = g_Qel + ((long long)b * RP + r0) * CC;
    const bf* Bh = g_Xh + (long long)b * CC * NTOK + n0;
    const bf* Bl = g_Xl + (long long)b * CC * NTOK + n0;

    for (int kc = 0; kc < 4; kc++) {
        __syncthreads();
        copy_tile(smem + A_HI, Ah + kc * 64, 128, CC, tid);
        copy_tile(smem + A_LO, Al + kc * 64, 128, CC, tid);
        // B: 64 c-rows x 160 n-cols, row pitch 336 B
        for (int idx = tid; idx < 64 * 20; idx += 256) {
            int r = idx / 20, c8 = idx % 20;
            long long goff = (long long)(kc * 64 + r) * NTOK + c8 * 8;
            *(uint4*)(smem + B_HI + r * B1P + c8 * 16) = *(const uint4*)(Bh + goff);
            *(uint4*)(smem + B_LO + r * B1P + c8 * 16) = *(const uint4*)(Bl + goff);
        }
        __syncthreads();

#pragma unroll
        for (int ks = 0; ks < 4; ks++) {
            uint32_t ah[4][4], al[4][4], bh[5][2], bl[5][2];
            const uint32_t kbyte = ks * 32 + (lane >> 4) * 16;
#pragma unroll
            for (int mf = 0; mf < 4; mf++) {
                uint32_t row = wm * 64 + mf * 16 + (lane & 15);
                uint32_t off = row * 128 + kbyte;
                off ^= (off >> 3) & 0x70;
                ldsm4(ah[mf], sb + A_HI + off);
                ldsm4(al[mf], sb + A_LO + off);
            }
            const uint32_t crow = ks * 16 + (lane & 15);
#pragma unroll
            for (int nf = 0; nf < 5; nf++) {
                uint32_t off = crow * B1P + (wn * 40 + nf * 8) * 2;
                ldsm2t(bh[nf], sb + B_HI + off);
                ldsm2t(bl[nf], sb + B_LO + off);
            }
#pragma unroll
            for (int mf = 0; mf < 4; mf++)
#pragma unroll
                for (int nf = 0; nf < 5; nf++) {
                    mma_bf16(acc[mf][nf], ah[mf], bh[nf]);
                    mma_bf16(acc[mf][nf], ah[mf], bl[nf]);
                    mma_bf16(acc[mf][nf], al[mf], bh[nf]);
                }
        }
    }

    float* Out = g_S + ((long long)b * RP + r0 + wm * 64) * NTOK + n0 + wn * 40;
    const int rr = lane >> 2, cc2 = (lane & 3) * 2;
#pragma unroll
    for (int mf = 0; mf < 4; mf++)
#pragma unroll
        for (int nf = 0; nf < 5; nf++) {
            float* o = Out + (long long)(mf * 16 + rr) * NTOK + nf * 8 + cc2;
            *(float2*)o = make_float2(acc[mf][nf][0], acc[mf][nf][1]);
            *(float2*)(o + 8LL * NTOK) = make_float2(acc[mf][nf][2], acc[mf][nf][3]);
        }
}

// ==================== GEMM2: Y[b][r][c] = P @ X^T (contract n=1600) ====================
// Block 128(r) x 128(c); warps 2(m) x 4(n) -> warp tile 64 x 32. Both operands K-major.
__global__ __launch_bounds__(256, 1)
void gemm2_mma() {
    extern __shared__ char smem[];
    constexpr int A_HI = 0, A_LO = 16384, B_HI = 32768, B_LO = 49152;
    const int b = blockIdx.z, r0 = blockIdx.y * 128, c0 = blockIdx.x * 128;
    const int tid = threadIdx.x, lane = tid & 31, wid = tid >> 5;
    const int wm = wid >> 2, wn = wid & 3;
    const uint32_t sb = smem_u32(smem);

    float acc[4][4][4];
#pragma unroll
    for (int i = 0; i < 4; i++)
#pragma unroll
        for (int j = 0; j < 4; j++)
#pragma unroll
            for (int k = 0; k < 4; k++) acc[i][j][k] = 0.f;

    const bf* Ah = g_Ph + ((long long)b * RP + r0) * NTOK;
    const bf* Al = g_Pl + ((long long)b * RP + r0) * NTOK;
    const bf* Bh = g_Xh + ((long long)b * CC + c0) * NTOK;
    const bf* Bl = g_Xl + ((long long)b * CC + c0) * NTOK;

    for (int kc = 0; kc < 25; kc++) {
        __syncthreads();
        copy_tile(smem + A_HI, Ah + kc * 64, 128, NTOK, tid);
        copy_tile(smem + A_LO, Al + kc * 64, 128, NTOK, tid);
        copy_tile(smem + B_HI, Bh + kc * 64, 128, NTOK, tid);
        copy_tile(smem + B_LO, Bl + kc * 64, 128, NTOK, tid);
        __syncthreads();

#pragma unroll
        for (int ks = 0; ks < 4; ks++) {
            uint32_t ah[4][4], al[4][4], bh[4][2], bl[4][2];
            const uint32_t kbyte = ks * 32 + (lane >> 4) * 16;
#pragma unroll
            for (int mf = 0; mf < 4; mf++) {
                uint32_t row = wm * 64 + mf * 16 + (lane & 15);
                uint32_t off = row * 128 + kbyte;
                off ^= (off >> 3) & 0x70;
                ldsm4(ah[mf], sb + A_HI + off);
                ldsm4(al[mf], sb + A_LO + off);
            }
            const uint32_t kb2 = ks * 32 + ((lane & 15) >> 3) * 16;
#pragma unroll
            for (int nf = 0; nf < 4; nf++) {
                uint32_t row = wn * 32 + nf * 8 + (lane & 7);
                uint32_t off = row * 128 + kb2;
                off ^= (off >> 3) & 0x70;
                ldsm2(bh[nf], sb + B_HI + off);
                ldsm2(bl[nf], sb + B_LO + off);
            }
#pragma unroll
            for (int mf = 0; mf < 4; mf++)
#pragma unroll
                for (int nf = 0; nf < 4; nf++) {
                    mma_bf16(acc[mf][nf], ah[mf], bh[nf]);
                    mma_bf16(acc[mf][nf], ah[mf], bl[nf]);
                    mma_bf16(acc[mf][nf], al[mf], bh[nf]);
                }
        }
    }

    float* Out = g_Y + ((long long)b * RP + r0 + wm * 64) * CC + c0 + wn * 32;
    const int rr = lane >> 2, cc2 = (lane & 3) * 2;
#pragma unroll
    for (int mf = 0; mf < 4; mf++)
#pragma unroll
        for (int nf = 0; nf < 4; nf++) {
            float* o = Out + (long long)(mf * 16 + rr) * CC + nf * 8 + cc2;
            *(float2*)o = make_float2(acc[mf][nf][0], acc[mf][nf][1]);
            *(float2*)(o + 8LL * CC) = make_float2(acc[mf][nf][2], acc[mf][nf][3]);
        }
}

// ==================== support kernels ====================

// Weff[h][co][c] = sum_d proj_w[co][h*32+d] * v_w[h*32+d][c]
__global__ __launch_bounds__(256)
void weff_kernel(const float* __restrict__ pw, const float* __restrict__ vw) {
    const int h = blockIdx.x, co0 = blockIdx.y * 32, c = threadIdx.x;
    float vv[HD];
#pragma unroll
    for (int d = 0; d < HD; d++) vv[d] = vw[(h * HD + d) * CC + c];
    for (int i = 0; i < 32; i++) {
        const int co = co0 + i;
        float a = 0.f;
#pragma unroll
        for (int d = 0; d < HD; d++) a += pw[co * CC + h * HD + d] * vv[d];
        g_We[(h * CC + co) * CC + c] = a;
    }
}

// Qeff (bf16 hi/lo); pad rows never written (stay zero).
__global__ __launch_bounds__(256)
void qeff_kernel(const float* __restrict__ x_cls, const float* __restrict__ qw,
                 const float* __restrict__ kw, const float* __restrict__ temp) {
    const int b = blockIdx.x, t = threadIdx.x;
    __shared__ float buf[6528];

    for (int i = t; i < CC * VQ; i += 256) buf[i] = x_cls[b * CC * VQ + i];
    __syncthreads();

    float acc[VQ];
#pragma unroll
    for (int v = 0; v < VQ; v++) acc[v] = 0.f;
    const float* wrow = qw + t * CC;
    for (int c2 = 0; c2 < CC; c2++) {
        float w = wrow[c2];
#pragma unroll
        for (int v = 0; v < VQ; v++) acc[v] += w * buf[c2 * VQ + v];
    }
    const float s = temp[t >> 5] * 0.17677669529663687f;
    __syncthreads();
#pragma unroll
    for (int v = 0; v < VQ; v++) buf[v * 260 + t] = acc[v] * s;
    __syncthreads();

    for (int h = 0; h < HH; h++) {
        float kv[HD];
#pragma unroll
        for (int d = 0; d < HD; d++) kv[d] = kw[(h * HD + d) * CC + t];
        for (int v = 0; v < VQ; v++) {
            float a = 0.f;
#pragma unroll
            for (int d = 0; d < HD; d++) a += buf[v * 260 + h * HD + d] * kv[d];
            bf hi, lo; split_bf(a, hi, lo);
            const long long idx = ((long long)b * RP + h * VQ + v) * CC + t;
            g_Qeh[idx] = hi;
            g_Qel[idx] = lo;
        }
    }
}

// Streaming split of x_patch into bf16 hi/lo (natural [b][c][n] layout).
__global__ __launch_bounds__(256)
void convx_kernel(const float* __restrict__ xp) {
    const long long i = ((long long)blockIdx.x * 256 + threadIdx.x) * 4;
    float4 v = *(const float4*)(xp + i);
    bf h0, l0, h1, l1, h2, l2, h3, l3;
    split_bf(v.x, h0, l0); split_bf(v.y, h1, l1);
    split_bf(v.z, h2, l2); split_bf(v.w, h3, l3);
    __nv_bfloat162* ph = (__nv_bfloat162*)(g_Xh + i);
    __nv_bfloat162* pl = (__nv_bfloat162*)(g_Xl + i);
    ph[0] = __nv_bfloat162(h0, h1); ph[1] = __nv_bfloat162(h2, h3);
    pl[0] = __nv_bfloat162(l0, l1); pl[1] = __nv_bfloat162(l2, l3);
}

// Row softmax over g_S rows r<200; emit bf16 hi/lo probabilities.
__global__ __launch_bounds__(256)
void softmax_kernel() {
    const int wid = threadIdx.x >> 5, lane = threadIdx.x & 31;
    const int r = blockIdx.x * 8 + wid, b = blockIdx.y;
    const float* p = g_S + ((long long)b * RP + r) * NTOK;

    float v[50];
    float mx = -1e30f;
#pragma unroll
    for (int i = 0; i < 50; i++) { v[i] = p[i * 32 + lane]; mx = fmaxf(mx, v[i]); }
#pragma unroll
    for (int o = 16; o; o >>= 1) mx = fmaxf(mx, __shfl_xor_sync(0xffffffffu, mx, o));
    float s = 0.f;
#pragma unroll
    for (int i = 0; i < 50; i++) { float e = __expf(v[i] - mx); v[i] = e; s += e; }
#pragma unroll
    for (int o = 16; o; o >>= 1) s += __shfl_xor_sync(0xffffffffu, s, o);
    const float inv = 1.f / s;

    bf* ph = g_Ph + ((long long)b * RP + r) * NTOK;
    bf* pl = g_Pl + ((long long)b * RP + r) * NTOK;
#pragma unroll
    for (int i = 0; i < 50; i++) {
        bf hi, lo; split_bf(v[i] * inv, hi, lo);
        ph[i * 32 + lane] = hi;
        pl[i * 32 + lane] = lo;
    }
}

// Final: out[b][co][v] = proj_b[co] + sum_h sum_c We[h][co][c] * Y[b][h*25+v][c]
__global__ __launch_bounds__(256)
void final_kernel(const float* __restrict__ pb, float* __restrict__ out) {
    const int b = blockIdx.x, gy = blockIdx.y, t = threadIdx.x;
    __shared__ float ys[256 * 27 + 32];

    const int nv = (gy == 0) ? 7 : 6;
    float acc[7];
    const float bias = pb[t];
#pragma unroll
    for (int k = 0; k < 7; k++) acc[k] = bias;

    for (int h = 0; h < HH; h++) {
        __syncthreads();
        for (int i = t; i < VQ * CC; i += 256) {
            int v = i >> 8, c = i & 255;
            ys[c * 27 + v] = g_Y[((long long)b * RP + h * VQ + v) * CC + c];
        }
        __syncthreads();
        const float* we = g_We + (h * CC + t) * CC;
        for (int c = 0; c < CC; c++) {
            float w = we[c];
#pragma unroll
            for (int k = 0; k < 7; k++)
                acc[k] += w * ys[c * 27 + gy + 4 * k];
        }
    }
    for (int k = 0; k < nv; k++)
        out[b * (CC * VQ) + t * VQ + gy + 4 * k] = acc[k];
}

// ---------------------------------------------------------------
extern "C" void kernel_launch(void* const* d_in, const int* in_sizes, int n_in,
                              void* d_out, int out_size) {
    (void)in_sizes; (void)n_in; (void)out_size;
    const float* x_cls   = (const float*)d_in[0];
    const float* x_patch = (const float*)d_in[1];
    const float* q_w     = (const float*)d_in[2];
    const float* k_w     = (const float*)d_in[3];
    const float* v_w     = (const float*)d_in[4];
    const float* temp    = (const float*)d_in[5];
    const float* proj_w  = (const float*)d_in[6];
    const float* proj_b  = (const float*)d_in[7];
    float* out = (float*)d_out;

    const int SMEM1 = 32768 + 2 * 64 * B1P;   // 75776
    const int SMEM2 = 65536;
    static int configured = 0;
    cudaFuncSetAttribute(gemm1_mma, cudaFuncAttributeMaxDynamicSharedMemorySize, SMEM1);
    cudaFuncSetAttribute(gemm2_mma, cudaFuncAttributeMaxDynamicSharedMemorySize, SMEM2);
    (void)configured;

    weff_kernel<<<dim3(HH, 8), 256>>>(proj_w, v_w);
    qeff_kernel<<<BB, 256>>>(x_cls, q_w, k_w, temp);
    convx_kernel<<<(BB * CC * NTOK) / 1024, 256>>>(x_patch);
    gemm1_mma<<<dim3(10, 2, BB), 256, SMEM1>>>();
    softmax_kernel<<<dim3(RR / 8, BB), 256>>>();
    gemm2_mma<<<dim3(2, 2, BB), 256, SMEM2>>>();
    final_kernel<<<dim3(BB, 4), 256>>>(proj_b, out);
}

// round 9
// speedup vs baseline: 2.0810x; 1.8806x over previous
#include <cuda_runtime.h>
#include <cuda_bf16.h>
#include <cstdint>

#define BB   64
#define CC   256
#define NTOK 1600
#define VQ   25
#define HH   8
#define HD   32
#define RR   200
#define RP   256

typedef __nv_bfloat16 bf;

// -------- device scratch (allocation-free rule; zero-init at load) --------
__device__ __align__(16) bf    g_Qeh[BB * RP * CC];   // pad rows 200..255 stay 0
__device__ __align__(16) bf    g_Qel[BB * RP * CC];
__device__ __align__(16) bf    g_Xh [BB * CC * NTOK];
__device__ __align__(16) bf    g_Xl [BB * CC * NTOK];
__device__ __align__(16) bf    g_Ph [BB * RP * NTOK]; // pad rows stay 0
__device__ __align__(16) bf    g_Pl [BB * RP * NTOK];
__device__ __align__(16) float g_S  [BB * RP * NTOK];
__device__ __align__(16) float g_Y  [BB * RP * CC];
__device__ __align__(16) float g_We [HH * CC * CC];

// ==================== PTX helpers (baseline ISA only) ====================
__device__ __forceinline__ uint32_t smem_u32(const void* p) {
    uint32_t a;
    asm("{ .reg .u64 t; cvta.to.shared.u64 t, %1; cvt.u32.u64 %0, t; }" : "=r"(a) : "l"(p));
    return a;
}
__device__ __forceinline__ void ldsm4(uint32_t* r, uint32_t a) {
    asm volatile("ldmatrix.sync.aligned.m8n8.x4.shared.b16 {%0,%1,%2,%3}, [%4];"
                 : "=r"(r[0]), "=r"(r[1]), "=r"(r[2]), "=r"(r[3]) : "r"(a));
}
__device__ __forceinline__ void ldsm2(uint32_t* r, uint32_t a) {
    asm volatile("ldmatrix.sync.aligned.m8n8.x2.shared.b16 {%0,%1}, [%2];"
                 : "=r"(r[0]), "=r"(r[1]) : "r"(a));
}
__device__ __forceinline__ void ldsm2t(uint32_t* r, uint32_t a) {
    asm volatile("ldmatrix.sync.aligned.m8n8.x2.trans.shared.b16 {%0,%1}, [%2];"
                 : "=r"(r[0]), "=r"(r[1]) : "r"(a));
}
__device__ __forceinline__ void mma_bf16(float* c, const uint32_t* a, const uint32_t* b) {
    asm volatile("mma.sync.aligned.m16n8k16.row.col.f32.bf16.bf16.f32 "
                 "{%0,%1,%2,%3}, {%4,%5,%6,%7}, {%8,%9}, {%0,%1,%2,%3};"
                 : "+f"(c[0]), "+f"(c[1]), "+f"(c[2]), "+f"(c[3])
                 : "r"(a[0]), "r"(a[1]), "r"(a[2]), "r"(a[3]), "r"(b[0]), "r"(b[1]));
}
__device__ __forceinline__ void cp16(uint32_t d, const void* g) {
    asm volatile("cp.async.cg.shared.global [%0], [%1], 16;" :: "r"(d), "l"(g) : "memory");
}
#define CP_COMMIT() asm volatile("cp.async.commit_group;" ::: "memory")
#define CP_WAIT(n)  asm volatile("cp.async.wait_group %0;" :: "n"(n) : "memory")

__device__ __forceinline__ void split_bf(float v, bf& h, bf& l) {
    h = __float2bfloat16(v);
    l = __float2bfloat16(v - __bfloat162float(h));
}

// ==================== GEMM1: S[b][r][n] = Qe @ X (contract c=256) ====================
// Block 128(r) x 160(n); warps 2(m) x 4(n) -> warp tile 64 x 40.
// cp.async double-buffered: load chunk kc+1 while computing kc.
#define B1P 336   // padded B row bytes: 168 bf16
#define STG1 75776
__global__ __launch_bounds__(256, 1)
void gemm1_mma() {
    extern __shared__ char smem[];
    constexpr int A_HI = 0, A_LO = 16384, B_HI = 32768, B_LO = 32768 + 64 * B1P;
    const int b = blockIdx.z, r0 = blockIdx.y * 128, n0 = blockIdx.x * 160;
    const int tid = threadIdx.x, lane = tid & 31, wid = tid >> 5;
    const int wm = wid >> 2, wn = wid & 3;
    const uint32_t sb = smem_u32(smem);

    float acc[4][5][4];
#pragma unroll
    for (int i = 0; i < 4; i++)
#pragma unroll
        for (int j = 0; j < 5; j++)
#pragma unroll
            for (int k = 0; k < 4; k++) acc[i][j][k] = 0.f;

    const bf* Ah = g_Qeh + ((long long)b * RP + r0) * CC;
    const bf* Al = g_Qel + ((long long)b * RP + r0) * CC;
    const bf* Bh = g_Xh + (long long)b * CC * NTOK + n0;
    const bf* Bl = g_Xl + (long long)b * CC * NTOK + n0;

    auto load = [&](int kc, int st) {
        const uint32_t base = sb + st * STG1;
#pragma unroll
        for (int it = 0; it < 4; it++) {
            int idx = tid + it * 256;
            int r = idx >> 3, c = idx & 7;
            uint32_t off = (uint32_t)(r * 128 + c * 16);
            off ^= (off >> 3) & 0x70;
            const long long go = (long long)r * CC + kc * 64 + c * 8;
            cp16(base + A_HI + off, Ah + go);
            cp16(base + A_LO + off, Al + go);
        }
#pragma unroll
        for (int it = 0; it < 5; it++) {
            int idx = tid + it * 256;
            int r = idx / 20, c8 = idx % 20;
            const long long go = (long long)(kc * 64 + r) * NTOK + c8 * 8;
            cp16(base + B_HI + r * B1P + c8 * 16, Bh + go);
            cp16(base + B_LO + r * B1P + c8 * 16, Bl + go);
        }
    };

    load(0, 0);
    CP_COMMIT();

    for (int kc = 0; kc < 4; kc++) {
        if (kc + 1 < 4) {
            load(kc + 1, (kc + 1) & 1);
            CP_COMMIT();
            CP_WAIT(1);
        } else {
            CP_WAIT(0);
        }
        __syncthreads();

        const uint32_t base = sb + (kc & 1) * STG1;
#pragma unroll
        for (int ks = 0; ks < 4; ks++) {
            uint32_t ah[4][4], al[4][4], bh[5][2], bl[5][2];
            const uint32_t kbyte = ks * 32 + (lane >> 4) * 16;
#pragma unroll
            for (int mf = 0; mf < 4; mf++) {
                uint32_t row = wm * 64 + mf * 16 + (lane & 15);
                uint32_t off = row * 128 + kbyte;
                off ^= (off >> 3) & 0x70;
                ldsm4(ah[mf], base + A_HI + off);
                ldsm4(al[mf], base + A_LO + off);
            }
            const uint32_t crow = ks * 16 + (lane & 15);
#pragma unroll
            for (int nf = 0; nf < 5; nf++) {
                uint32_t off = crow * B1P + (wn * 40 + nf * 8) * 2;
                ldsm2t(bh[nf], base + B_HI + off);
                ldsm2t(bl[nf], base + B_LO + off);
            }
#pragma unroll
            for (int mf = 0; mf < 4; mf++)
#pragma unroll
                for (int nf = 0; nf < 5; nf++) {
                    mma_bf16(acc[mf][nf], ah[mf], bh[nf]);
                    mma_bf16(acc[mf][nf], ah[mf], bl[nf]);
                    mma_bf16(acc[mf][nf], al[mf], bh[nf]);
                }
        }
        __syncthreads();
    }

    float* Out = g_S + ((long long)b * RP + r0 + wm * 64) * NTOK + n0 + wn * 40;
    const int rr = lane >> 2, cc2 = (lane & 3) * 2;
#pragma unroll
    for (int mf = 0; mf < 4; mf++)
#pragma unroll
        for (int nf = 0; nf < 5; nf++) {
            float* o = Out + (long long)(mf * 16 + rr) * NTOK + nf * 8 + cc2;
            *(float2*)o = make_float2(acc[mf][nf][0], acc[mf][nf][1]);
            *(float2*)(o + 8LL * NTOK) = make_float2(acc[mf][nf][2], acc[mf][nf][3]);
        }
}

// ==================== GEMM2: Y[b][r][c] = P @ X^T (contract n=1600) ====================
// Block 128(r) x 128(c); warps 2(m) x 4(n) -> warp tile 64 x 32. Both operands K-major.
#define STG2 65536
__global__ __launch_bounds__(256, 1)
void gemm2_mma() {
    extern __shared__ char smem[];
    constexpr int A_HI = 0, A_LO = 16384, B_HI = 32768, B_LO = 49152;
    const int b = blockIdx.z, r0 = blockIdx.y * 128, c0 = blockIdx.x * 128;
    const int tid = threadIdx.x, lane = tid & 31, wid = tid >> 5;
    const int wm = wid >> 2, wn = wid & 3;
    const uint32_t sb = smem_u32(smem);

    float acc[4][4][4];
#pragma unroll
    for (int i = 0; i < 4; i++)
#pragma unroll
        for (int j = 0; j < 4; j++)
#pragma unroll
            for (int k = 0; k < 4; k++) acc[i][j][k] = 0.f;

    const bf* Ah = g_Ph + ((long long)b * RP + r0) * NTOK;
    const bf* Al = g_Pl + ((long long)b * RP + r0) * NTOK;
    const bf* Bh = g_Xh + ((long long)b * CC + c0) * NTOK;
    const bf* Bl = g_Xl + ((long long)b * CC + c0) * NTOK;

    auto load = [&](int kc, int st) {
        const uint32_t base = sb + st * STG2;
#pragma unroll
        for (int it = 0; it < 4; it++) {
            int idx = tid + it * 256;
            int r = idx >> 3, c = idx & 7;
            uint32_t off = (uint32_t)(r * 128 + c * 16);
            off ^= (off >> 3) & 0x70;
            const long long ga = (long long)r * NTOK + kc * 64 + c * 8;
            cp16(base + A_HI + off, Ah + ga);
            cp16(base + A_LO + off, Al + ga);
            cp16(base + B_HI + off, Bh + ga);
            cp16(base + B_LO + off, Bl + ga);
        }
    };

    load(0, 0);
    CP_COMMIT();

    for (int kc = 0; kc < 25; kc++) {
        if (kc + 1 < 25) {
            load(kc + 1, (kc + 1) & 1);
            CP_COMMIT();
            CP_WAIT(1);
        } else {
            CP_WAIT(0);
        }
        __syncthreads();

        const uint32_t base = sb + (kc & 1) * STG2;
#pragma unroll
        for (int ks = 0; ks < 4; ks++) {
            uint32_t ah[4][4], al[4][4], bh[4][2], bl[4][2];
            const uint32_t kbyte = ks * 32 + (lane >> 4) * 16;
#pragma unroll
            for (int mf = 0; mf < 4; mf++) {
                uint32_t row = wm * 64 + mf * 16 + (lane & 15);
                uint32_t off = row * 128 + kbyte;
                off ^= (off >> 3) & 0x70;
                ldsm4(ah[mf], base + A_HI + off);
                ldsm4(al[mf], base + A_LO + off);
            }
            const uint32_t kb2 = ks * 32 + ((lane & 15) >> 3) * 16;
#pragma unroll
            for (int nf = 0; nf < 4; nf++) {
                uint32_t row = wn * 32 + nf * 8 + (lane & 7);
                uint32_t off = row * 128 + kb2;
                off ^= (off >> 3) & 0x70;
                ldsm2(bh[nf], base + B_HI + off);
                ldsm2(bl[nf], base + B_LO + off);
            }
#pragma unroll
            for (int mf = 0; mf < 4; mf++)
#pragma unroll
                for (int nf = 0; nf < 4; nf++) {
                    mma_bf16(acc[mf][nf], ah[mf], bh[nf]);
                    mma_bf16(acc[mf][nf], ah[mf], bl[nf]);
                    mma_bf16(acc[mf][nf], al[mf], bh[nf]);
                }
        }
        __syncthreads();
    }

    float* Out = g_Y + ((long long)b * RP + r0 + wm * 64) * CC + c0 + wn * 32;
    const int rr = lane >> 2, cc2 = (lane & 3) * 2;
#pragma unroll
    for (int mf = 0; mf < 4; mf++)
#pragma unroll
        for (int nf = 0; nf < 4; nf++) {
            float* o = Out + (long long)(mf * 16 + rr) * CC + nf * 8 + cc2;
            *(float2*)o = make_float2(acc[mf][nf][0], acc[mf][nf][1]);
            *(float2*)(o + 8LL * CC) = make_float2(acc[mf][nf][2], acc[mf][nf][3]);
        }
}

// ==================== support kernels ====================

// Weff[h][co][c] = sum_d proj_w[co][h*32+d] * v_w[h*32+d][c]
__global__ __launch_bounds__(256)
void weff_kernel(const float* __restrict__ pw, const float* __restrict__ vw) {
    const int h = blockIdx.x, co0 = blockIdx.y * 32, c = threadIdx.x;
    float vv[HD];
#pragma unroll
    for (int d = 0; d < HD; d++) vv[d] = vw[(h * HD + d) * CC + c];
    for (int i = 0; i < 32; i++) {
        const int co = co0 + i;
        float a = 0.f;
#pragma unroll
        for (int d = 0; d < HD; d++) a += pw[co * CC + h * HD + d] * vv[d];
        g_We[(h * CC + co) * CC + c] = a;
    }
}

// Qeff (bf16 hi/lo); pad rows never written (stay zero).
__global__ __launch_bounds__(256)
void qeff_kernel(const float* __restrict__ x_cls, const float* __restrict__ qw,
                 const float* __restrict__ kw, const float* __restrict__ temp) {
    const int b = blockIdx.x, t = threadIdx.x;
    __shared__ float buf[6528];

    for (int i = t; i < CC * VQ; i += 256) buf[i] = x_cls[b * CC * VQ + i];
    __syncthreads();

    float acc[VQ];
#pragma unroll
    for (int v = 0; v < VQ; v++) acc[v] = 0.f;
    const float* wrow = qw + t * CC;
    for (int c2 = 0; c2 < CC; c2++) {
        float w = wrow[c2];
#pragma unroll
        for (int v = 0; v < VQ; v++) acc[v] += w * buf[c2 * VQ + v];
    }
    const float s = temp[t >> 5] * 0.17677669529663687f;
    __syncthreads();
#pragma unroll
    for (int v = 0; v < VQ; v++) buf[v * 260 + t] = acc[v] * s;
    __syncthreads();

    for (int h = 0; h < HH; h++) {
        float kv[HD];
#pragma unroll
        for (int d = 0; d < HD; d++) kv[d] = kw[(h * HD + d) * CC + t];
        for (int v = 0; v < VQ; v++) {
            float a = 0.f;
#pragma unroll
            for (int d = 0; d < HD; d++) a += buf[v * 260 + h * HD + d] * kv[d];
            bf hi, lo; split_bf(a, hi, lo);
            const long long idx = ((long long)b * RP + h * VQ + v) * CC + t;
            g_Qeh[idx] = hi;
            g_Qel[idx] = lo;
        }
    }
}

// Streaming split of x_patch into bf16 hi/lo (natural [b][c][n] layout).
__global__ __launch_bounds__(256)
void convx_kernel(const float* __restrict__ xp) {
    const long long i = ((long long)blockIdx.x * 256 + threadIdx.x) * 4;
    float4 v = *(const float4*)(xp + i);
    bf h0, l0, h1, l1, h2, l2, h3, l3;
    split_bf(v.x, h0, l0); split_bf(v.y, h1, l1);
    split_bf(v.z, h2, l2); split_bf(v.w, h3, l3);
    __nv_bfloat162* ph = (__nv_bfloat162*)(g_Xh + i);
    __nv_bfloat162* pl = (__nv_bfloat162*)(g_Xl + i);
    ph[0] = __nv_bfloat162(h0, h1); ph[1] = __nv_bfloat162(h2, h3);
    pl[0] = __nv_bfloat162(l0, l1); pl[1] = __nv_bfloat162(l2, l3);
}

// Row softmax over g_S rows r<200; emit bf16 hi/lo probabilities.
__global__ __launch_bounds__(256)
void softmax_kernel() {
    const int wid = threadIdx.x >> 5, lane = threadIdx.x & 31;
    const int r = blockIdx.x * 8 + wid, b = blockIdx.y;
    const float* p = g_S + ((long long)b * RP + r) * NTOK;

    float v[50];
    float mx = -1e30f;
#pragma unroll
    for (int i = 0; i < 50; i++) { v[i] = p[i * 32 + lane]; mx = fmaxf(mx, v[i]); }
#pragma unroll
    for (int o = 16; o; o >>= 1) mx = fmaxf(mx, __shfl_xor_sync(0xffffffffu, mx, o));
    float s = 0.f;
#pragma unroll
    for (int i = 0; i < 50; i++) { float e = __expf(v[i] - mx); v[i] = e; s += e; }
#pragma unroll
    for (int o = 16; o; o >>= 1) s += __shfl_xor_sync(0xffffffffu, s, o);
    const float inv = 1.f / s;

    bf* ph = g_Ph + ((long long)b * RP + r) * NTOK;
    bf* pl = g_Pl + ((long long)b * RP + r) * NTOK;
#pragma unroll
    for (int i = 0; i < 50; i++) {
        bf hi, lo; split_bf(v[i] * inv, hi, lo);
        ph[i * 32 + lane] = hi;
        pl[i * 32 + lane] = lo;
    }
}

// Final: out[b][co][v] = proj_b[co] + sum_h sum_c We[h][co][c] * Y[b][h*25+v][c]
__global__ __launch_bounds__(256)
void final_kernel(const float* __restrict__ pb, float* __restrict__ out) {
    const int b = blockIdx.x, gy = blockIdx.y, t = threadIdx.x;
    __shared__ float ys[256 * 27 + 32];

    const int nv = (gy == 0) ? 7 : 6;
    float acc[7];
    const float bias = pb[t];
#pragma unroll
    for (int k = 0; k < 7; k++) acc[k] = bias;

    for (int h = 0; h < HH; h++) {
        __syncthreads();
        for (int i = t; i < VQ * CC; i += 256) {
            int v = i >> 8, c = i & 255;
            ys[c * 27 + v] = g_Y[((long long)b * RP + h * VQ + v) * CC + c];
        }
        __syncthreads();
        const float* we = g_We + (h * CC + t) * CC;
        for (int c = 0; c < CC; c++) {
            float w = we[c];
#pragma unroll
            for (int k = 0; k < 7; k++)
                acc[k] += w * ys[c * 27 + gy + 4 * k];
        }
    }
    for (int k = 0; k < nv; k++)
        out[b * (CC * VQ) + t * VQ + gy + 4 * k] = acc[k];
}

// ---------------------------------------------------------------
extern "C" void kernel_launch(void* const* d_in, const int* in_sizes, int n_in,
                              void* d_out, int out_size) {
    (void)in_sizes; (void)n_in; (void)out_size;
    const float* x_cls   = (const float*)d_in[0];
    const float* x_patch = (const float*)d_in[1];
    const float* q_w     = (const float*)d_in[2];
    const float* k_w     = (const float*)d_in[3];
    const float* v_w     = (const float*)d_in[4];
    const float* temp    = (const float*)d_in[5];
    const float* proj_w  = (const float*)d_in[6];
    const float* proj_b  = (const float*)d_in[7];
    float* out = (float*)d_out;

    const int SMEM1 = 2 * STG1;   // 151552
    const int SMEM2 = 2 * STG2;   // 131072
    cudaFuncSetAttribute(gemm1_mma, cudaFuncAttributeMaxDynamicSharedMemorySize, SMEM1);
    cudaFuncSetAttribute(gemm2_mma, cudaFuncAttributeMaxDynamicSharedMemorySize, SMEM2);

    weff_kernel<<<dim3(HH, 8), 256>>>(proj_w, v_w);
    qeff_kernel<<<BB, 256>>>(x_cls, q_w, k_w, temp);
    convx_kernel<<<(BB * CC * NTOK) / 1024, 256>>>(x_patch);
    gemm1_mma<<<dim3(10, 2, BB), 256, SMEM1>>>();
    softmax_kernel<<<dim3(RR / 8, BB), 256>>>();
    gemm2_mma<<<dim3(2, 2, BB), 256, SMEM2>>>();
    final_kernel<<<dim3(BB, 4), 256>>>(proj_b, out);
}